// round 16
// baseline (speedup 1.0000x reference)
#include <cuda_runtime.h>
#include <math.h>

// ---------------- problem constants ----------------
#define BATCH 2
#define NCLS 24
#define NHEADS 8
#define CIN0 1024
#define CPROJ 128

typedef unsigned long long ull;

// ---------------- scratch (static device memory; no allocs) ----------------
__device__ __align__(16) float g_t0[(size_t)BATCH * 1024 * 4 * 6 * 8];
__device__ __align__(16) float g_t1[(size_t)BATCH * 512 * 8 * 12 * 16];
__device__ __align__(16) float g_t2[(size_t)BATCH * 256 * 16 * 24 * 32];
__device__ __align__(16) float g_t3[(size_t)BATCH * 128 * 32 * 48 * 64];
__device__ __align__(16) float g_t4[(size_t)BATCH * 32 * 64 * 96 * 128];
__device__ __align__(16) float g_pL1[(size_t)BATCH * 4 * 512 * 8 * 12 * 16];
__device__ __align__(16) float g_part[1024 * 16 * 2];
__device__ __align__(16) float g_scale[1024];
__device__ __align__(16) float g_shift[1024];

// ---------------- packed f32x2 / async helpers ----------------
__device__ __forceinline__ void fma2(ull& d, ull a, ull b) {
    asm("fma.rn.f32x2 %0, %1, %2, %0;" : "+l"(d) : "l"(a), "l"(b));
}
__device__ __forceinline__ ull pack2f(float lo, float hi) {
    ull r;
    asm("mov.b64 %0, {%1, %2};" : "=l"(r) : "f"(lo), "f"(hi));
    return r;
}
__device__ __forceinline__ float2 unpk2(ull v) {
    float2 r;
    asm("mov.b64 {%0, %1}, %2;" : "=f"(r.x), "=f"(r.y) : "l"(v));
    return r;
}
__device__ __forceinline__ void cpasync4(unsigned dst, const float* src) {
    asm volatile("cp.async.ca.shared.global [%0], [%1], 4;" ::"r"(dst), "l"(src)
                 : "memory");
}
__device__ __forceinline__ void cp_commit() {
    asm volatile("cp.async.commit_group;" ::: "memory");
}
__device__ __forceinline__ void cp_wait0() {
    asm volatile("cp.async.wait_group 0;" ::: "memory");
}

// ---------------- fused hypernet + projection ----------------
__global__ void hyperproj_kernel(const float* __restrict__ x,
                                 const float* __restrict__ y,
                                 const float* __restrict__ tables,
                                 float* __restrict__ out) {
    const int S = 192;
    const int s = threadIdx.x;  // 0..191
    const int hb = blockIdx.x;  // 0..127
    const int b = blockIdx.y;
    const int K = CPROJ * CIN0;
    const int h = (hb * 8) / CPROJ;
    const int obase = (hb * 8) % CPROJ;

    __shared__ float wsh[8 * 1024];

    float yreg[NCLS];
#pragma unroll
    for (int q = 0; q < NCLS; q++) yreg[q] = y[b * NCLS + q];

    for (int i = s; i < 8 * 1024; i += 192) {
        int j = i >> 10;
        int c = i & 1023;
        const float* t = tables + (size_t)h * NCLS * K + (size_t)(obase + j) * 1024 + c;
        float a = 0.f;
#pragma unroll
        for (int q = 0; q < NCLS; q++) a = fmaf(yreg[q], t[(size_t)q * K], a);
        wsh[i] = a;
    }
    __syncthreads();

    const float* xb = x + (size_t)b * 1024 * S + s;
    float acc[8];
#pragma unroll
    for (int j = 0; j < 8; j++) acc[j] = 0.f;
    for (int c = 0; c < 1024; c++) {
        float xv = xb[(size_t)c * S];
#pragma unroll
        for (int j = 0; j < 8; j++) acc[j] = fmaf(wsh[j * 1024 + c], xv, acc[j]);
    }
#pragma unroll
    for (int j = 0; j < 8; j++)
        out[((size_t)b * 1024 + hb * 8 + j) * S + s] = acc[j];
}

// ---------------- BatchNorm ----------------
#define BN_NB 16
__global__ void bn_partial(const float* __restrict__ x, int C, int S,
                           float* __restrict__ part) {
    int c = blockIdx.x;
    int nb = blockIdx.y;
    int n = BATCH * S;
    float s1 = 0.f, s2 = 0.f;
    for (int e = nb * blockDim.x + threadIdx.x; e < n; e += BN_NB * blockDim.x) {
        int bb = e / S;
        int sp = e - bb * S;
        float v = x[((size_t)bb * C + c) * S + sp];
        s1 += v;
        s2 += v * v;
    }
    __shared__ float r1[256];
    __shared__ float r2[256];
    r1[threadIdx.x] = s1;
    r2[threadIdx.x] = s2;
    __syncthreads();
    for (int st = 128; st > 0; st >>= 1) {
        if (threadIdx.x < st) {
            r1[threadIdx.x] += r1[threadIdx.x + st];
            r2[threadIdx.x] += r2[threadIdx.x + st];
        }
        __syncthreads();
    }
    if (threadIdx.x == 0) {
        part[(c * BN_NB + nb) * 2 + 0] = r1[0];
        part[(c * BN_NB + nb) * 2 + 1] = r2[0];
    }
}

__global__ void bn_finalize(const float* __restrict__ part, int C, float n,
                            const float* __restrict__ g, const float* __restrict__ be,
                            float* __restrict__ scale, float* __restrict__ shift) {
    int c = blockIdx.x * blockDim.x + threadIdx.x;
    if (c >= C) return;
    float s1 = 0.f, s2 = 0.f;
    for (int i = 0; i < BN_NB; i++) {
        s1 += part[(c * BN_NB + i) * 2 + 0];
        s2 += part[(c * BN_NB + i) * 2 + 1];
    }
    float mean = s1 / n;
    float var = s2 / n - mean * mean;
    var = fmaxf(var, 0.f);
    float sc = g[c] * rsqrtf(var + 1e-5f);
    scale[c] = sc;
    shift[c] = be[c] - mean * sc;
}

// one-block-per-channel fused BN stats (layer 0 only: n = 384)
__global__ void bn_stats_one(const float* __restrict__ x, int C, int S,
                             const float* __restrict__ g,
                             const float* __restrict__ be,
                             float* __restrict__ scale, float* __restrict__ shift) {
    int c = blockIdx.x;
    int n = BATCH * S;
    float s1 = 0.f, s2 = 0.f;
    for (int e = threadIdx.x; e < n; e += blockDim.x) {
        int bb = e / S;
        int sp = e - bb * S;
        float v = x[((size_t)bb * C + c) * S + sp];
        s1 += v;
        s2 += v * v;
    }
    __shared__ float r1[128];
    __shared__ float r2[128];
    r1[threadIdx.x] = s1;
    r2[threadIdx.x] = s2;
    __syncthreads();
    for (int st = 64; st > 0; st >>= 1) {
        if (threadIdx.x < st) {
            r1[threadIdx.x] += r1[threadIdx.x + st];
            r2[threadIdx.x] += r2[threadIdx.x + st];
        }
        __syncthreads();
    }
    if (threadIdx.x == 0) {
        float mean = r1[0] / n;
        float var = r2[0] / n - mean * mean;
        var = fmaxf(var, 0.f);
        float sc = g[c] * rsqrtf(var + 1e-5f);
        scale[c] = sc;
        shift[c] = be[c] - mean * sc;
    }
}

// float4 BN apply + ReLU (S always divisible by 4)
__global__ void bn_apply_relu4(float* __restrict__ x, int C, int S,
                               const float* __restrict__ scale,
                               const float* __restrict__ shift) {
    size_t gid = (size_t)blockIdx.x * blockDim.x + threadIdx.x;
    size_t total4 = (size_t)BATCH * C * (S / 4);
    if (gid >= total4) return;
    int c = (int)((gid * 4 / S) % C);
    float sc = scale[c], sh = shift[c];
    float4 v = reinterpret_cast<float4*>(x)[gid];
    v.x = fmaxf(fmaf(v.x, sc, sh), 0.f);
    v.y = fmaxf(fmaf(v.y, sc, sh), 0.f);
    v.z = fmaxf(fmaf(v.z, sc, sh), 0.f);
    v.w = fmaxf(fmaf(v.w, sc, sh), 0.f);
    reinterpret_cast<float4*>(x)[gid] = v;
}

// ---------------- L1 partial combine: t1 = sum_{s<4} p[b,s] + bias ----------
__global__ void combine4_kernel(const float* __restrict__ p,
                                const float* __restrict__ bias,
                                float* __restrict__ outp, int Cout, int OS) {
    size_t gid = (size_t)blockIdx.x * blockDim.x + threadIdx.x;
    size_t per_b = (size_t)Cout * OS;
    size_t total = (size_t)BATCH * per_b;
    if (gid >= total) return;
    int b = (int)(gid / per_b);
    size_t r = gid - (size_t)b * per_b;
    int c = (int)(r / OS);
    const float* pb = p + (size_t)(b * 4) * per_b + r;
    outp[gid] = pb[0] + pb[per_b] + pb[2 * per_b] + pb[3 * per_b] + bias[c];
}

// ---------------- ConvTranspose3d k=4 s=2 p=1 : f32x2, OC chans/thread,
//                  QC-channel groups + cp.async staging, optional Cin split,
//                  MINB forces min blocks/SM (reg cap) ----------------------
// Per dim: out px=0 taps (d=0,k=1),(d=-1,k=3) ; px=1 taps (d=+1,k=0),(d=0,k=2).
// Cell m: px0 += v[m]*w1 + v[m-1]*w3 ; px1 += v[m+1]*w0 + v[m]*w2.
// De-interleaved staged layout (even x at cols [0..TXc], odd at [OB..OB+TXc]).
// Buffers hold QC channels; next QC staged by cp.async while computing current;
// ONE barrier per QC channels. Halo zero-filled once. Requires QC <= CC.
template <int TILEY, int TILEX, int RW, int OB, int PSPAD, int OG, int OC, int CC,
          int QC, int NSPLIT, int MINB, bool SIG>
__global__ void __launch_bounds__(TILEY * TILEX * OG, MINB)
convt14_kernel(const float* __restrict__ in, const float* __restrict__ wt,
               const float* __restrict__ bias, float* __restrict__ out,
               int Cin, int Cout, int Dz, int Hy, int Wx, int ntx, int nty) {
    constexpr int TXc = TILEX / 2;
    constexpr int TYc = TILEY / 2;
    constexpr int NTS = TILEY * TILEX;
    constexpr int NT = NTS * OG;
    constexpr int PH = TILEY + 2;
    constexpr int PS = PH * RW + PSPAD;  // plane stride (words)
    constexpr int SDLP = 6 * PS;
    constexpr int RMAX = (SDLP + NT - 1) / NT;
    constexpr int WPC = OG * OC * CC * 32;

    __shared__ float vsm[2][QC * SDLP];
    __shared__ ull wsmU[2][WPC];

    const int tid = threadIdx.x;
    const int og = tid / NTS;
    const int s = tid - og * NTS;
    const int obase = blockIdx.y * OG * OC + og * OC;
    const int zid = blockIdx.z;
    const int b = zid / NSPLIT;
    const int CLEN = Cin / NSPLIT;
    const int cbeg = (zid - b * NSPLIT) * CLEN;
    const int tile = blockIdx.x;
    const int tix = tile % ntx;
    const int t2 = tile / ntx;
    const int tiy = t2 % nty;
    const int tiz = t2 / nty;

    const int txi = s % TXc;
    const int t3 = s / TXc;
    const int tyi = t3 % TYc;
    const int tzi = t3 / TYc;  // 0..3

    const int bz = tiz * 4, by = tiy * TILEY, bx = tix * TILEX;
    const int S = Dz * Hy * Wx;
    const float* inb = in + (size_t)b * Cin * S;

    // channel-invariant staging offsets into the de-interleaved layout
    int soff[RMAX];
    unsigned sw_vld = 0;
#pragma unroll
    for (int r = 0; r < RMAX; r++) {
        int idx = tid + r * NT;
        int i2 = idx < SDLP ? idx : 0;
        int plane = i2 / PS;
        int rem = i2 - plane * PS;
        int row = rem / RW;
        int col = rem - row * RW;
        bool inrow = (row < PH) && (idx < SDLP);
        bool iseven = col <= TXc;
        bool isodd = (col >= OB) && (col <= OB + TXc);
        bool act = inrow && (iseven || isodd);
        int px = iseven ? 2 * col : 2 * (col - OB) + 1;
        int gz = bz + plane - 1, gy = by + row - 1, gx = bx + px - 1;
        bool vld = act && (gz >= 0 && gz < Dz) && (gy >= 0 && gy < Hy) &&
                   (gx >= 0 && gx < Wx);
        if (vld) sw_vld |= 1u << r;
        soff[r] = vld ? (gz * Hy + gy) * Wx + gx : 0;
    }

    auto stage_w = [&](int chunk) {  // absolute channel chunk
        ull* wd = wsmU[chunk & 1];
        for (int i = tid; i < WPC; i += NT) {
            int ogc = i / (CC * 32);
            int r = i - ogc * (CC * 32);
            int cl = r >> 5;
            int e = r & 31;
            int kzky = e >> 1;
            int half = e & 1;
            const float* wk = wt +
                (((size_t)(chunk * CC + cl)) * Cout +
                 (blockIdx.y * OG * OC + ogc)) * 64 +
                kzky * 4;
            float lo, hi;
            if (half == 0) { lo = wk[1]; hi = wk[0]; }
            else           { lo = wk[3]; hi = wk[2]; }
            wd[i] = pack2f(lo, hi);
        }
    };

    // async stage of QC channels (cfirst..cfirst+QC-1) into buffer pb
    auto stage_q = [&](int pb, int cfirst) {
        unsigned vb = (unsigned)__cvta_generic_to_shared(&vsm[pb][0]);
        const float* pc = inb + (size_t)cfirst * S;
#pragma unroll
        for (int r = 0; r < RMAX; r++) {
            if ((sw_vld >> r) & 1u) {
                unsigned d = vb + (unsigned)(tid + r * NT) * 4u;
#pragma unroll
                for (int q = 0; q < QC; q++)
                    cpasync4(d + (unsigned)(q * SDLP) * 4u, pc + (size_t)q * S + soff[r]);
            }
        }
    };

    ull acc[OC][2][2][4];
#pragma unroll
    for (int oc = 0; oc < OC; oc++)
#pragma unroll
        for (int cy = 0; cy < 2; cy++)
#pragma unroll
            for (int cx = 0; cx < 2; cx++)
#pragma unroll
                for (int p = 0; p < 4; p++) acc[oc][cy][cx][p] = 0ull;

    stage_w(cbeg / CC);
    // zero both buffers once (halo & dead cells stay 0 forever)
    for (int i = tid; i < 2 * QC * SDLP; i += NT) (&vsm[0][0])[i] = 0.f;
    __syncthreads();
    stage_q(0, cbeg);
    cp_commit();
    cp_wait0();
    __syncthreads();

    const int DDt[2][2] = {{0, -1}, {1, 0}};
    const int KKt[2][2] = {{1, 3}, {0, 2}};
    const int rbase = 2 * tyi * RW + txi;

    auto compute_ch = [&](const float* vb, const ull* wcU) {
#pragma unroll
        for (int jz = 0; jz < 3; jz++) {
            ull vp[4][3];
#pragma unroll
            for (int ry = 0; ry < 4; ry++) {
                const float* rp = vb + (tzi + jz) * PS + rbase + ry * RW;
                float e0 = rp[0];
                float e1 = rp[1];
                float o0 = rp[OB];
                float o1 = rp[OB + 1];
                vp[ry][0] = pack2f(e0, o0);
                vp[ry][1] = pack2f(o0, e1);
                vp[ry][2] = pack2f(e1, o1);
            }
#pragma unroll
            for (int pz = 0; pz < 2; pz++)
#pragma unroll
                for (int sz = 0; sz < 2; sz++) {
                    if (1 + DDt[pz][sz] != jz) continue;
                    const int kz = KKt[pz][sz];
#pragma unroll
                    for (int py = 0; py < 2; py++)
#pragma unroll
                        for (int sy = 0; sy < 2; sy++) {
                            const int jy0 = 1 + DDt[py][sy];
                            const int ky = KKt[py][sy];
#pragma unroll
                            for (int oc = 0; oc < OC; oc++) {
                                const ull wa =
                                    wcU[(oc * CC) * 32 + (kz * 4 + ky) * 2 + 0];
                                const ull wb =
                                    wcU[(oc * CC) * 32 + (kz * 4 + ky) * 2 + 1];
#pragma unroll
                                for (int cy = 0; cy < 2; cy++) {
                                    const int row = jy0 + cy;
#pragma unroll
                                    for (int cx = 0; cx < 2; cx++) {
                                        fma2(acc[oc][cy][cx][pz * 2 + py],
                                             vp[row][cx + 1], wa);
                                        fma2(acc[oc][cy][cx][pz * 2 + py],
                                             vp[row][cx], wb);
                                    }
                                }
                            }
                        }
                }
        }
    };

    for (int ci = 0; ci < CLEN; ci += QC) {
        const int c = cbeg + ci;
        if ((ci & (CC - 1)) == 0 && ci + CC < CLEN) stage_w(c / CC + 1);
        const bool havenext = (ci + QC < CLEN);
        if (havenext) {
            stage_q(((ci / QC) + 1) & 1, c + QC);
            cp_commit();
        }

        const float* vb = vsm[(ci / QC) & 1];
        const ull* wbase = wsmU[(c / CC) & 1] + (size_t)og * OC * CC * 32;
#pragma unroll
        for (int q = 0; q < QC; q++)
            compute_ch(vb + q * SDLP, wbase + ((c + q) & (CC - 1)) * 32);

        if (havenext) cp_wait0();
        __syncthreads();
    }

    // ---------------- epilogue (scalar stores; exact tiling) ----------------
    const int mz = bz + tzi;
    if (mz >= Dz) return;
    const int Ho = 2 * Hy, Wo = 2 * Wx;
    const int my0 = by + 2 * tyi;
    const int mx0 = bx + 2 * txi;

#pragma unroll
    for (int oc = 0; oc < OC; oc++) {
        const int o = obase + oc;
        const float bv = (NSPLIT > 1) ? 0.f : bias[o];
        float* ob = out + ((size_t)zid * Cout + o) * (size_t)(2 * Dz) * Ho * Wo;
#pragma unroll
        for (int cy = 0; cy < 2; cy++) {
            int my = my0 + cy;
            if (my >= Hy) continue;
#pragma unroll
            for (int cx = 0; cx < 2; cx++) {
                int mx = mx0 + cx;
                if (mx >= Wx) continue;
#pragma unroll
                for (int pz = 0; pz < 2; pz++)
#pragma unroll
                    for (int py = 0; py < 2; py++) {
                        float2 a = unpk2(acc[oc][cy][cx][pz * 2 + py]);
                        float r0 = a.x + bv;
                        float r1 = a.y + bv;
                        if (SIG) {
                            r0 = 1.f / (1.f + __expf(-r0));
                            r1 = 1.f / (1.f + __expf(-r1));
                        }
                        size_t base = (size_t)(2 * mz + pz) * Ho * Wo +
                                      (size_t)(2 * my + py) * Wo + (size_t)(2 * mx);
                        ob[base] = r0;
                        ob[base + 1] = r1;
                    }
            }
        }
    }
}

// ---------------- host-side helpers ----------------
static void run_bn(float* t, int C, int S, const float* g, const float* be,
                   float* part, float* scale, float* shift) {
    dim3 gp(C, BN_NB);
    bn_partial<<<gp, 256>>>(t, C, S, part);
    bn_finalize<<<(C + 127) / 128, 128>>>(part, C, (float)(BATCH * S), g, be,
                                          scale, shift);
    size_t total4 = (size_t)BATCH * C * S / 4;
    bn_apply_relu4<<<(unsigned)((total4 + 255) / 256), 256>>>(t, C, S, scale,
                                                              shift);
}

template <int TILEY, int TILEX, int RW, int OB, int PSPAD, int OG, int OC, int CC,
          int QC, int NSPLIT, int MINB, bool SIG>
static void run_convt14(const float* in, const float* wt, const float* bias,
                        float* out, int Cin, int Cout, int Dz, int Hy, int Wx) {
    int ntx = Wx / TILEX;
    int nty = Hy / TILEY;
    int ntz = Dz / 4;
    dim3 grid(ntx * nty * ntz, Cout / (OG * OC), BATCH * NSPLIT);
    convt14_kernel<TILEY, TILEX, RW, OB, PSPAD, OG, OC, CC, QC, NSPLIT, MINB, SIG>
        <<<grid, TILEY * TILEX * OG>>>(in, wt, bias, out, Cin, Cout, Dz, Hy, Wx,
                                       ntx, nty);
}

extern "C" void kernel_launch(void* const* d_in, const int* in_sizes, int n_in,
                              void* d_out, int out_size) {
    const float* x_in = (const float*)d_in[0];
    const float* y_in = (const float*)d_in[1];
    const float* tables = (const float*)d_in[2];
    const float* g0 = (const float*)d_in[3];
    const float* be0 = (const float*)d_in[4];
    const float* g1 = (const float*)d_in[5];
    const float* be1 = (const float*)d_in[6];
    const float* g2 = (const float*)d_in[7];
    const float* be2 = (const float*)d_in[8];
    const float* g3 = (const float*)d_in[9];
    const float* be3 = (const float*)d_in[10];
    const float* g4 = (const float*)d_in[11];
    const float* be4 = (const float*)d_in[12];
    const float* w1 = (const float*)d_in[13];
    const float* b1 = (const float*)d_in[14];
    const float* w2 = (const float*)d_in[15];
    const float* b2 = (const float*)d_in[16];
    const float* w3 = (const float*)d_in[17];
    const float* b3 = (const float*)d_in[18];
    const float* w4 = (const float*)d_in[19];
    const float* b4 = (const float*)d_in[20];
    const float* w5 = (const float*)d_in[21];
    const float* b5 = (const float*)d_in[22];

    float *t0, *t1, *t2, *t3, *t4, *pL1, *part, *scale, *shift;
    cudaGetSymbolAddress((void**)&t0, g_t0);
    cudaGetSymbolAddress((void**)&t1, g_t1);
    cudaGetSymbolAddress((void**)&t2, g_t2);
    cudaGetSymbolAddress((void**)&t3, g_t3);
    cudaGetSymbolAddress((void**)&t4, g_t4);
    cudaGetSymbolAddress((void**)&pL1, g_pL1);
    cudaGetSymbolAddress((void**)&part, g_part);
    cudaGetSymbolAddress((void**)&scale, g_scale);
    cudaGetSymbolAddress((void**)&shift, g_shift);

    // 1) fused hypernet + projection -> t0 [2,1024,4,6,8]
    {
        dim3 pg(128, BATCH);
        hyperproj_kernel<<<pg, 192>>>(x_in, y_in, tables, t0);
    }
    // 2) L0 BN (fused stats) -> convt L1 (split 4-way over Cin) is launch #4
    bn_stats_one<<<1024, 128>>>(t0, 1024, 4 * 6 * 8, g0, be0, scale, shift);
    {
        size_t total4 = (size_t)BATCH * 1024 * 192 / 4;
        bn_apply_relu4<<<(unsigned)((total4 + 255) / 256), 256>>>(
            t0, 1024, 192, scale, shift);
    }
    // L1: unchanged config (MINB=1 -> same codegen as R15's winner)
    run_convt14<6, 8, 18, 8, 28, 2, 2, 8, 2, 4, 1, false>(t0, w1, b1, pL1, 1024,
                                                          512, 4, 6, 8);
    {
        int OS = 8 * 12 * 16;
        size_t tot = (size_t)BATCH * 512 * OS;
        combine4_kernel<<<(unsigned)((tot + 255) / 256), 256>>>(pL1, b1, t1, 512,
                                                                OS);
    }
    run_bn(t1, 512, 8 * 12 * 16, g1, be1, part, scale, shift);
    // L2-L5: QC=2 (smem ~23-27KB) + forced 4 blocks/SM (reg cap 128)
    run_convt14<4, 16, 24, 12, 24, 2, 2, 4, 2, 1, 4, false>(t1, w2, b2, t2, 512,
                                                            256, 8, 12, 16);
    run_bn(t2, 256, 16 * 24 * 32, g2, be2, part, scale, shift);
    run_convt14<8, 16, 20, 10, 0, 1, 2, 8, 2, 1, 4, false>(t2, w3, b3, t3, 256,
                                                           128, 16, 24, 32);
    run_bn(t3, 128, 32 * 48 * 64, g3, be3, part, scale, shift);
    run_convt14<8, 16, 20, 10, 0, 1, 2, 8, 2, 1, 4, false>(t3, w4, b4, t4, 128,
                                                           32, 32, 48, 64);
    run_bn(t4, 32, 64 * 96 * 128, g4, be4, part, scale, shift);
    run_convt14<8, 16, 20, 10, 0, 1, 1, 8, 2, 1, 4, true>(t4, w5, b5,
                                                          (float*)d_out, 32, 1,
                                                          64, 96, 128);
}

// round 17
// speedup vs baseline: 1.1558x; 1.1558x over previous
#include <cuda_runtime.h>
#include <math.h>

// ---------------- problem constants ----------------
#define BATCH 2
#define NCLS 24
#define NHEADS 8
#define CIN0 1024
#define CPROJ 128

typedef unsigned long long ull;

// ---------------- scratch (static device memory; no allocs) ----------------
__device__ __align__(16) float g_t0[(size_t)BATCH * 1024 * 4 * 6 * 8];
__device__ __align__(16) float g_t1[(size_t)BATCH * 512 * 8 * 12 * 16];
__device__ __align__(16) float g_t2[(size_t)BATCH * 256 * 16 * 24 * 32];
__device__ __align__(16) float g_t3[(size_t)BATCH * 128 * 32 * 48 * 64];
__device__ __align__(16) float g_t4[(size_t)BATCH * 32 * 64 * 96 * 128];
__device__ __align__(16) float g_pL1[(size_t)BATCH * 4 * 512 * 8 * 12 * 16];
__device__ __align__(16) float g_part[1024 * 16 * 2];
__device__ __align__(16) float g_scale[1024];
__device__ __align__(16) float g_shift[1024];

// ---------------- packed f32x2 / async helpers ----------------
__device__ __forceinline__ void fma2(ull& d, ull a, ull b) {
    asm("fma.rn.f32x2 %0, %1, %2, %0;" : "+l"(d) : "l"(a), "l"(b));
}
__device__ __forceinline__ ull pack2f(float lo, float hi) {
    ull r;
    asm("mov.b64 %0, {%1, %2};" : "=l"(r) : "f"(lo), "f"(hi));
    return r;
}
__device__ __forceinline__ float2 unpk2(ull v) {
    float2 r;
    asm("mov.b64 {%0, %1}, %2;" : "=f"(r.x), "=f"(r.y) : "l"(v));
    return r;
}
__device__ __forceinline__ void cpasync4(unsigned dst, const float* src) {
    asm volatile("cp.async.ca.shared.global [%0], [%1], 4;" ::"r"(dst), "l"(src)
                 : "memory");
}
__device__ __forceinline__ void cp_commit() {
    asm volatile("cp.async.commit_group;" ::: "memory");
}
__device__ __forceinline__ void cp_wait0() {
    asm volatile("cp.async.wait_group 0;" ::: "memory");
}

// ---------------- fused hypernet + projection ----------------
__global__ void hyperproj_kernel(const float* __restrict__ x,
                                 const float* __restrict__ y,
                                 const float* __restrict__ tables,
                                 float* __restrict__ out) {
    const int S = 192;
    const int s = threadIdx.x;  // 0..191
    const int hb = blockIdx.x;  // 0..127
    const int b = blockIdx.y;
    const int K = CPROJ * CIN0;
    const int h = (hb * 8) / CPROJ;
    const int obase = (hb * 8) % CPROJ;

    __shared__ float wsh[8 * 1024];

    float yreg[NCLS];
#pragma unroll
    for (int q = 0; q < NCLS; q++) yreg[q] = y[b * NCLS + q];

    for (int i = s; i < 8 * 1024; i += 192) {
        int j = i >> 10;
        int c = i & 1023;
        const float* t = tables + (size_t)h * NCLS * K + (size_t)(obase + j) * 1024 + c;
        float a = 0.f;
#pragma unroll
        for (int q = 0; q < NCLS; q++) a = fmaf(yreg[q], t[(size_t)q * K], a);
        wsh[i] = a;
    }
    __syncthreads();

    const float* xb = x + (size_t)b * 1024 * S + s;
    float acc[8];
#pragma unroll
    for (int j = 0; j < 8; j++) acc[j] = 0.f;
    for (int c = 0; c < 1024; c++) {
        float xv = xb[(size_t)c * S];
#pragma unroll
        for (int j = 0; j < 8; j++) acc[j] = fmaf(wsh[j * 1024 + c], xv, acc[j]);
    }
#pragma unroll
    for (int j = 0; j < 8; j++)
        out[((size_t)b * 1024 + hb * 8 + j) * S + s] = acc[j];
}

// ---------------- BatchNorm ----------------
#define BN_NB 16
__global__ void bn_partial(const float* __restrict__ x, int C, int S,
                           float* __restrict__ part) {
    int c = blockIdx.x;
    int nb = blockIdx.y;
    int n = BATCH * S;
    float s1 = 0.f, s2 = 0.f;
    for (int e = nb * blockDim.x + threadIdx.x; e < n; e += BN_NB * blockDim.x) {
        int bb = e / S;
        int sp = e - bb * S;
        float v = x[((size_t)bb * C + c) * S + sp];
        s1 += v;
        s2 += v * v;
    }
    __shared__ float r1[256];
    __shared__ float r2[256];
    r1[threadIdx.x] = s1;
    r2[threadIdx.x] = s2;
    __syncthreads();
    for (int st = 128; st > 0; st >>= 1) {
        if (threadIdx.x < st) {
            r1[threadIdx.x] += r1[threadIdx.x + st];
            r2[threadIdx.x] += r2[threadIdx.x + st];
        }
        __syncthreads();
    }
    if (threadIdx.x == 0) {
        part[(c * BN_NB + nb) * 2 + 0] = r1[0];
        part[(c * BN_NB + nb) * 2 + 1] = r2[0];
    }
}

__global__ void bn_finalize(const float* __restrict__ part, int C, float n,
                            const float* __restrict__ g, const float* __restrict__ be,
                            float* __restrict__ scale, float* __restrict__ shift) {
    int c = blockIdx.x * blockDim.x + threadIdx.x;
    if (c >= C) return;
    float s1 = 0.f, s2 = 0.f;
    for (int i = 0; i < BN_NB; i++) {
        s1 += part[(c * BN_NB + i) * 2 + 0];
        s2 += part[(c * BN_NB + i) * 2 + 1];
    }
    float mean = s1 / n;
    float var = s2 / n - mean * mean;
    var = fmaxf(var, 0.f);
    float sc = g[c] * rsqrtf(var + 1e-5f);
    scale[c] = sc;
    shift[c] = be[c] - mean * sc;
}

// one-block-per-channel fused BN stats (layer 0 only: n = 384)
__global__ void bn_stats_one(const float* __restrict__ x, int C, int S,
                             const float* __restrict__ g,
                             const float* __restrict__ be,
                             float* __restrict__ scale, float* __restrict__ shift) {
    int c = blockIdx.x;
    int n = BATCH * S;
    float s1 = 0.f, s2 = 0.f;
    for (int e = threadIdx.x; e < n; e += blockDim.x) {
        int bb = e / S;
        int sp = e - bb * S;
        float v = x[((size_t)bb * C + c) * S + sp];
        s1 += v;
        s2 += v * v;
    }
    __shared__ float r1[128];
    __shared__ float r2[128];
    r1[threadIdx.x] = s1;
    r2[threadIdx.x] = s2;
    __syncthreads();
    for (int st = 64; st > 0; st >>= 1) {
        if (threadIdx.x < st) {
            r1[threadIdx.x] += r1[threadIdx.x + st];
            r2[threadIdx.x] += r2[threadIdx.x + st];
        }
        __syncthreads();
    }
    if (threadIdx.x == 0) {
        float mean = r1[0] / n;
        float var = r2[0] / n - mean * mean;
        var = fmaxf(var, 0.f);
        float sc = g[c] * rsqrtf(var + 1e-5f);
        scale[c] = sc;
        shift[c] = be[c] - mean * sc;
    }
}

// float4 BN apply + ReLU (S always divisible by 4)
__global__ void bn_apply_relu4(float* __restrict__ x, int C, int S,
                               const float* __restrict__ scale,
                               const float* __restrict__ shift) {
    size_t gid = (size_t)blockIdx.x * blockDim.x + threadIdx.x;
    size_t total4 = (size_t)BATCH * C * (S / 4);
    if (gid >= total4) return;
    int c = (int)((gid * 4 / S) % C);
    float sc = scale[c], sh = shift[c];
    float4 v = reinterpret_cast<float4*>(x)[gid];
    v.x = fmaxf(fmaf(v.x, sc, sh), 0.f);
    v.y = fmaxf(fmaf(v.y, sc, sh), 0.f);
    v.z = fmaxf(fmaf(v.z, sc, sh), 0.f);
    v.w = fmaxf(fmaf(v.w, sc, sh), 0.f);
    reinterpret_cast<float4*>(x)[gid] = v;
}

// ---------------- L1 partial combine: t1 = sum_{s<4} p[b,s] + bias ----------
__global__ void combine4_kernel(const float* __restrict__ p,
                                const float* __restrict__ bias,
                                float* __restrict__ outp, int Cout, int OS) {
    size_t gid = (size_t)blockIdx.x * blockDim.x + threadIdx.x;
    size_t per_b = (size_t)Cout * OS;
    size_t total = (size_t)BATCH * per_b;
    if (gid >= total) return;
    int b = (int)(gid / per_b);
    size_t r = gid - (size_t)b * per_b;
    int c = (int)(r / OS);
    const float* pb = p + (size_t)(b * 4) * per_b + r;
    outp[gid] = pb[0] + pb[per_b] + pb[2 * per_b] + pb[3 * per_b] + bias[c];
}

// ---------------- ConvTranspose3d k=4 s=2 p=1 : f32x2, OC chans/thread,
//                  QC-channel groups + cp.async staging, optional Cin split,
//                  weights read as one aligned ulonglong2 LDS.128 -----------
// Per dim: out px=0 taps (d=0,k=1),(d=-1,k=3) ; px=1 taps (d=+1,k=0),(d=0,k=2).
// Cell m: px0 += v[m]*w1 + v[m-1]*w3 ; px1 += v[m+1]*w0 + v[m]*w2.
// De-interleaved staged layout (even x at cols [0..TXc], odd at [OB..OB+TXc]).
// Buffers hold QC channels; next QC staged by cp.async while computing current;
// ONE barrier per QC channels. Halo zero-filled once. Requires QC <= CC.
// NSPLIT>1: blockIdx.z = b*NSPLIT+split; partial outputs, bias in combine.
template <int TILEY, int TILEX, int RW, int OB, int PSPAD, int OG, int OC, int CC,
          int QC, int NSPLIT, bool SIG>
__global__ void __launch_bounds__(TILEY * TILEX * OG)
convt15_kernel(const float* __restrict__ in, const float* __restrict__ wt,
               const float* __restrict__ bias, float* __restrict__ out,
               int Cin, int Cout, int Dz, int Hy, int Wx, int ntx, int nty) {
    constexpr int TXc = TILEX / 2;
    constexpr int TYc = TILEY / 2;
    constexpr int NTS = TILEY * TILEX;
    constexpr int NT = NTS * OG;
    constexpr int PH = TILEY + 2;
    constexpr int PS = PH * RW + PSPAD;  // plane stride (words)
    constexpr int SDLP = 6 * PS;
    constexpr int RMAX = (SDLP + NT - 1) / NT;
    constexpr int WPC2 = OG * OC * CC * 16;  // ulonglong2 entries per chunk

    __shared__ float vsm[2][QC * SDLP];
    __shared__ __align__(16) ulonglong2 wsm2[2][WPC2];

    const int tid = threadIdx.x;
    const int og = tid / NTS;
    const int s = tid - og * NTS;
    const int obase = blockIdx.y * OG * OC + og * OC;
    const int zid = blockIdx.z;
    const int b = zid / NSPLIT;
    const int CLEN = Cin / NSPLIT;
    const int cbeg = (zid - b * NSPLIT) * CLEN;
    const int tile = blockIdx.x;
    const int tix = tile % ntx;
    const int t2 = tile / ntx;
    const int tiy = t2 % nty;
    const int tiz = t2 / nty;

    const int txi = s % TXc;
    const int t3 = s / TXc;
    const int tyi = t3 % TYc;
    const int tzi = t3 / TYc;  // 0..3

    const int bz = tiz * 4, by = tiy * TILEY, bx = tix * TILEX;
    const int S = Dz * Hy * Wx;
    const float* inb = in + (size_t)b * Cin * S;

    // channel-invariant staging offsets into the de-interleaved layout
    int soff[RMAX];
    unsigned sw_vld = 0;
#pragma unroll
    for (int r = 0; r < RMAX; r++) {
        int idx = tid + r * NT;
        int i2 = idx < SDLP ? idx : 0;
        int plane = i2 / PS;
        int rem = i2 - plane * PS;
        int row = rem / RW;
        int col = rem - row * RW;
        bool inrow = (row < PH) && (idx < SDLP);
        bool iseven = col <= TXc;
        bool isodd = (col >= OB) && (col <= OB + TXc);
        bool act = inrow && (iseven || isodd);
        int px = iseven ? 2 * col : 2 * (col - OB) + 1;
        int gz = bz + plane - 1, gy = by + row - 1, gx = bx + px - 1;
        bool vld = act && (gz >= 0 && gz < Dz) && (gy >= 0 && gy < Hy) &&
                   (gx >= 0 && gx < Wx);
        if (vld) sw_vld |= 1u << r;
        soff[r] = vld ? (gz * Hy + gy) * Wx + gx : 0;
    }

    auto stage_w = [&](int chunk) {  // absolute channel chunk
        ulonglong2* wd = wsm2[chunk & 1];
        for (int i = tid; i < WPC2; i += NT) {
            int ogc = i / (CC * 16);
            int r = i - ogc * (CC * 16);
            int cl = r >> 4;
            int kk = r & 15;
            const float* wk = wt +
                (((size_t)(chunk * CC + cl)) * Cout +
                 (blockIdx.y * OG * OC + ogc)) * 64 +
                kk * 4;
            ulonglong2 p;
            p.x = pack2f(wk[1], wk[0]);  // (w1, w0)
            p.y = pack2f(wk[3], wk[2]);  // (w3, w2)
            wd[i] = p;
        }
    };

    // async stage of QC channels (cfirst..cfirst+QC-1) into buffer pb
    auto stage_q = [&](int pb, int cfirst) {
        unsigned vb = (unsigned)__cvta_generic_to_shared(&vsm[pb][0]);
        const float* pc = inb + (size_t)cfirst * S;
#pragma unroll
        for (int r = 0; r < RMAX; r++) {
            if ((sw_vld >> r) & 1u) {
                unsigned d = vb + (unsigned)(tid + r * NT) * 4u;
#pragma unroll
                for (int q = 0; q < QC; q++)
                    cpasync4(d + (unsigned)(q * SDLP) * 4u, pc + (size_t)q * S + soff[r]);
            }
        }
    };

    ull acc[OC][2][2][4];
#pragma unroll
    for (int oc = 0; oc < OC; oc++)
#pragma unroll
        for (int cy = 0; cy < 2; cy++)
#pragma unroll
            for (int cx = 0; cx < 2; cx++)
#pragma unroll
                for (int p = 0; p < 4; p++) acc[oc][cy][cx][p] = 0ull;

    stage_w(cbeg / CC);
    // zero both buffers once (halo & dead cells stay 0 forever)
    for (int i = tid; i < 2 * QC * SDLP; i += NT) (&vsm[0][0])[i] = 0.f;
    __syncthreads();
    stage_q(0, cbeg);
    cp_commit();
    cp_wait0();
    __syncthreads();

    const int DDt[2][2] = {{0, -1}, {1, 0}};
    const int KKt[2][2] = {{1, 3}, {0, 2}};
    const int rbase = 2 * tyi * RW + txi;

    auto compute_ch = [&](const float* vb, const ulonglong2* wcU) {
#pragma unroll
        for (int jz = 0; jz < 3; jz++) {
            ull vp[4][3];
#pragma unroll
            for (int ry = 0; ry < 4; ry++) {
                const float* rp = vb + (tzi + jz) * PS + rbase + ry * RW;
                float e0 = rp[0];
                float e1 = rp[1];
                float o0 = rp[OB];
                float o1 = rp[OB + 1];
                vp[ry][0] = pack2f(e0, o0);
                vp[ry][1] = pack2f(o0, e1);
                vp[ry][2] = pack2f(e1, o1);
            }
#pragma unroll
            for (int pz = 0; pz < 2; pz++)
#pragma unroll
                for (int sz = 0; sz < 2; sz++) {
                    if (1 + DDt[pz][sz] != jz) continue;
                    const int kz = KKt[pz][sz];
#pragma unroll
                    for (int py = 0; py < 2; py++)
#pragma unroll
                        for (int sy = 0; sy < 2; sy++) {
                            const int jy0 = 1 + DDt[py][sy];
                            const int ky = KKt[py][sy];
#pragma unroll
                            for (int oc = 0; oc < OC; oc++) {
                                // one aligned LDS.128: (w1,w0)|(w3,w2)
                                const ulonglong2 w2 =
                                    wcU[oc * CC * 16 + kz * 4 + ky];
#pragma unroll
                                for (int cy = 0; cy < 2; cy++) {
                                    const int row = jy0 + cy;
#pragma unroll
                                    for (int cx = 0; cx < 2; cx++) {
                                        fma2(acc[oc][cy][cx][pz * 2 + py],
                                             vp[row][cx + 1], w2.x);
                                        fma2(acc[oc][cy][cx][pz * 2 + py],
                                             vp[row][cx], w2.y);
                                    }
                                }
                            }
                        }
                }
        }
    };

    for (int ci = 0; ci < CLEN; ci += QC) {
        const int c = cbeg + ci;
        if ((ci & (CC - 1)) == 0 && ci + CC < CLEN) stage_w(c / CC + 1);
        const bool havenext = (ci + QC < CLEN);
        if (havenext) {
            stage_q(((ci / QC) + 1) & 1, c + QC);
            cp_commit();
        }

        const float* vb = vsm[(ci / QC) & 1];
        const ulonglong2* wbase = wsm2[(c / CC) & 1] + (size_t)og * OC * CC * 16;
#pragma unroll
        for (int q = 0; q < QC; q++)
            compute_ch(vb + q * SDLP, wbase + ((c + q) & (CC - 1)) * 16);

        if (havenext) cp_wait0();
        __syncthreads();
    }

    // ---------------- epilogue (scalar stores; exact tiling) ----------------
    const int mz = bz + tzi;
    if (mz >= Dz) return;
    const int Ho = 2 * Hy, Wo = 2 * Wx;
    const int my0 = by + 2 * tyi;
    const int mx0 = bx + 2 * txi;

#pragma unroll
    for (int oc = 0; oc < OC; oc++) {
        const int o = obase + oc;
        const float bv = (NSPLIT > 1) ? 0.f : bias[o];
        float* ob = out + ((size_t)zid * Cout + o) * (size_t)(2 * Dz) * Ho * Wo;
#pragma unroll
        for (int cy = 0; cy < 2; cy++) {
            int my = my0 + cy;
            if (my >= Hy) continue;
#pragma unroll
            for (int cx = 0; cx < 2; cx++) {
                int mx = mx0 + cx;
                if (mx >= Wx) continue;
#pragma unroll
                for (int pz = 0; pz < 2; pz++)
#pragma unroll
                    for (int py = 0; py < 2; py++) {
                        float2 a = unpk2(acc[oc][cy][cx][pz * 2 + py]);
                        float r0 = a.x + bv;
                        float r1 = a.y + bv;
                        if (SIG) {
                            r0 = 1.f / (1.f + __expf(-r0));
                            r1 = 1.f / (1.f + __expf(-r1));
                        }
                        size_t base = (size_t)(2 * mz + pz) * Ho * Wo +
                                      (size_t)(2 * my + py) * Wo + (size_t)(2 * mx);
                        ob[base] = r0;
                        ob[base + 1] = r1;
                    }
            }
        }
    }
}

// ---------------- host-side helpers ----------------
static void run_bn(float* t, int C, int S, const float* g, const float* be,
                   float* part, float* scale, float* shift) {
    dim3 gp(C, BN_NB);
    bn_partial<<<gp, 256>>>(t, C, S, part);
    bn_finalize<<<(C + 127) / 128, 128>>>(part, C, (float)(BATCH * S), g, be,
                                          scale, shift);
    size_t total4 = (size_t)BATCH * C * S / 4;
    bn_apply_relu4<<<(unsigned)((total4 + 255) / 256), 256>>>(t, C, S, scale,
                                                              shift);
}

template <int TILEY, int TILEX, int RW, int OB, int PSPAD, int OG, int OC, int CC,
          int QC, int NSPLIT, bool SIG>
static void run_convt15(const float* in, const float* wt, const float* bias,
                        float* out, int Cin, int Cout, int Dz, int Hy, int Wx) {
    int ntx = Wx / TILEX;
    int nty = Hy / TILEY;
    int ntz = Dz / 4;
    dim3 grid(ntx * nty * ntz, Cout / (OG * OC), BATCH * NSPLIT);
    convt15_kernel<TILEY, TILEX, RW, OB, PSPAD, OG, OC, CC, QC, NSPLIT, SIG>
        <<<grid, TILEY * TILEX * OG>>>(in, wt, bias, out, Cin, Cout, Dz, Hy, Wx,
                                       ntx, nty);
}

extern "C" void kernel_launch(void* const* d_in, const int* in_sizes, int n_in,
                              void* d_out, int out_size) {
    const float* x_in = (const float*)d_in[0];
    const float* y_in = (const float*)d_in[1];
    const float* tables = (const float*)d_in[2];
    const float* g0 = (const float*)d_in[3];
    const float* be0 = (const float*)d_in[4];
    const float* g1 = (const float*)d_in[5];
    const float* be1 = (const float*)d_in[6];
    const float* g2 = (const float*)d_in[7];
    const float* be2 = (const float*)d_in[8];
    const float* g3 = (const float*)d_in[9];
    const float* be3 = (const float*)d_in[10];
    const float* g4 = (const float*)d_in[11];
    const float* be4 = (const float*)d_in[12];
    const float* w1 = (const float*)d_in[13];
    const float* b1 = (const float*)d_in[14];
    const float* w2 = (const float*)d_in[15];
    const float* b2 = (const float*)d_in[16];
    const float* w3 = (const float*)d_in[17];
    const float* b3 = (const float*)d_in[18];
    const float* w4 = (const float*)d_in[19];
    const float* b4 = (const float*)d_in[20];
    const float* w5 = (const float*)d_in[21];
    const float* b5 = (const float*)d_in[22];

    float *t0, *t1, *t2, *t3, *t4, *pL1, *part, *scale, *shift;
    cudaGetSymbolAddress((void**)&t0, g_t0);
    cudaGetSymbolAddress((void**)&t1, g_t1);
    cudaGetSymbolAddress((void**)&t2, g_t2);
    cudaGetSymbolAddress((void**)&t3, g_t3);
    cudaGetSymbolAddress((void**)&t4, g_t4);
    cudaGetSymbolAddress((void**)&pL1, g_pL1);
    cudaGetSymbolAddress((void**)&part, g_part);
    cudaGetSymbolAddress((void**)&scale, g_scale);
    cudaGetSymbolAddress((void**)&shift, g_shift);

    // 1) fused hypernet + projection -> t0 [2,1024,4,6,8]
    {
        dim3 pg(128, BATCH);
        hyperproj_kernel<<<pg, 192>>>(x_in, y_in, tables, t0);
    }
    // 2) L0 BN (fused stats) -> convt L1 (split 4-way over Cin) is launch #4
    bn_stats_one<<<1024, 128>>>(t0, 1024, 4 * 6 * 8, g0, be0, scale, shift);
    {
        size_t total4 = (size_t)BATCH * 1024 * 192 / 4;
        bn_apply_relu4<<<(unsigned)((total4 + 255) / 256), 256>>>(
            t0, 1024, 192, scale, shift);
    }
    run_convt15<6, 8, 18, 8, 28, 2, 2, 8, 2, 4, false>(t0, w1, b1, pL1, 1024, 512,
                                                       4, 6, 8);
    {
        int OS = 8 * 12 * 16;
        size_t tot = (size_t)BATCH * 512 * OS;
        combine4_kernel<<<(unsigned)((tot + 255) / 256), 256>>>(pL1, b1, t1, 512,
                                                                OS);
    }
    run_bn(t1, 512, 8 * 12 * 16, g1, be1, part, scale, shift);
    run_convt15<4, 16, 24, 12, 24, 2, 2, 4, 4, 1, false>(t1, w2, b2, t2, 512, 256,
                                                         8, 12, 16);
    run_bn(t2, 256, 16 * 24 * 32, g2, be2, part, scale, shift);
    run_convt15<8, 16, 20, 10, 0, 1, 2, 4, 4, 1, false>(t2, w3, b3, t3, 256, 128,
                                                        16, 24, 32);
    run_bn(t3, 128, 32 * 48 * 64, g3, be3, part, scale, shift);
    run_convt15<8, 16, 20, 10, 0, 1, 2, 4, 4, 1, false>(t3, w4, b4, t4, 128, 32,
                                                        32, 48, 64);
    run_bn(t4, 32, 64 * 96 * 128, g4, be4, part, scale, shift);
    run_convt15<8, 16, 20, 10, 0, 1, 1, 8, 4, 1, true>(t4, w5, b5, (float*)d_out,
                                                       32, 1, 64, 96, 128);
}